// round 2
// baseline (speedup 1.0000x reference)
#include <cuda_runtime.h>
#include <math.h>

#define BATCH 4
#define SEQ   2048
#define EMB   512
#define NH    8
#define HD    64
#define MROWS (BATCH*SEQ)   // 8192

// Scratch (device globals: allocation-free per harness rules)
__device__ float g_Q[BATCH*NH*SEQ*HD];   // (b,h,n,d)
__device__ float g_K[BATCH*NH*SEQ*HD];
__device__ float g_V[BATCH*NH*SEQ*HD];
__device__ float g_AO[BATCH*SEQ*EMB];    // (b,n,e) attention output

// ---------------------------------------------------------------------------
// GEMM: C[m,e] = sum_k A[m,k] * W[e,k]   (A: MROWS x EMB row-major, W: EMB x EMB row-major)
// mode 0/1/2: write to g_Q/g_K/g_V in (b,h,n,d) layout (Q also could be scaled later)
// mode 3:     write plain row-major to dout
// Tile: BM=BN=64, BK=16, 256 threads, 4x4 micro-tile per thread.
// ---------------------------------------------------------------------------
__global__ __launch_bounds__(256) void gemm_nt(const float* __restrict__ A,
                                               const float* __restrict__ W,
                                               float* __restrict__ dout,
                                               int mode)
{
    __shared__ float Xs[16 * 68];   // Xs[k][m], pad 68 keeps float4 alignment
    __shared__ float Ws[16 * 68];   // Ws[k][e]

    const float* Ap = A ? A : g_AO;

    const int m0 = blockIdx.y * 64;
    const int e0 = blockIdx.x * 64;
    const int tid = threadIdx.x;
    const int tx = tid & 15;
    const int ty = tid >> 4;

    const int mm = tid >> 2;        // 0..63 : row within tile for loading
    const int k4 = (tid & 3) * 4;   // 0,4,8,12

    float acc[4][4] = {};

    for (int k0 = 0; k0 < EMB; k0 += 16) {
        float4 xa = *(const float4*)&Ap[(size_t)(m0 + mm) * EMB + k0 + k4];
        float4 wa = *(const float4*)&W [(size_t)(e0 + mm) * EMB + k0 + k4];
        __syncthreads();   // previous compute done before overwriting smem
        Xs[(k4 + 0) * 68 + mm] = xa.x;
        Xs[(k4 + 1) * 68 + mm] = xa.y;
        Xs[(k4 + 2) * 68 + mm] = xa.z;
        Xs[(k4 + 3) * 68 + mm] = xa.w;
        Ws[(k4 + 0) * 68 + mm] = wa.x;
        Ws[(k4 + 1) * 68 + mm] = wa.y;
        Ws[(k4 + 2) * 68 + mm] = wa.z;
        Ws[(k4 + 3) * 68 + mm] = wa.w;
        __syncthreads();
        #pragma unroll
        for (int k = 0; k < 16; k++) {
            float4 av = *(const float4*)&Xs[k * 68 + ty * 4];
            float4 bv = *(const float4*)&Ws[k * 68 + tx * 4];
            float a[4] = {av.x, av.y, av.z, av.w};
            float b[4] = {bv.x, bv.y, bv.z, bv.w};
            #pragma unroll
            for (int i = 0; i < 4; i++)
                #pragma unroll
                for (int j = 0; j < 4; j++)
                    acc[i][j] += a[i] * b[j];
        }
    }

    if (mode == 3) {
        #pragma unroll
        for (int i = 0; i < 4; i++) {
            int m = m0 + ty * 4 + i;
            float4 v = make_float4(acc[i][0], acc[i][1], acc[i][2], acc[i][3]);
            *(float4*)&dout[(size_t)m * EMB + e0 + tx * 4] = v;
        }
    } else {
        float* dst = (mode == 0) ? g_Q : (mode == 1) ? g_K : g_V;
        const int h = e0 >> 6;   // whole 64-wide e-tile lies inside one head
        #pragma unroll
        for (int i = 0; i < 4; i++) {
            int m = m0 + ty * 4 + i;
            int b = m >> 11;          // /SEQ
            int n = m & (SEQ - 1);
            float4 v = make_float4(acc[i][0], acc[i][1], acc[i][2], acc[i][3]);
            *(float4*)&dst[((size_t)(b * NH + h) * SEQ + n) * HD + tx * 4] = v;
        }
    }
}

// ---------------------------------------------------------------------------
// Causal flash attention, fp32. One CTA = one (b,h) x 64 query rows.
// Smem layouts (pad 68):
//   Qs[d][r]  (transposed, pre-scaled)    Ks[d][c] (transposed)
//   Vs[c][d]  (natural)                   Ps[c][r] (S/P transposed)
// ---------------------------------------------------------------------------
__global__ __launch_bounds__(256) void attn_kernel()
{
    extern __shared__ float sm[];
    float* Qs  = sm;
    float* Ks  = sm + 64 * 68;
    float* Vs  = sm + 2 * 64 * 68;
    float* Ps  = sm + 3 * 64 * 68;
    float* m_s = sm + 4 * 64 * 68;        // [64]
    float* l_s = m_s + 64;                // [64]
    float* a_s = l_s + 64;                // [64] rescale alpha

    const int bh = blockIdx.x;            // 0..31
    const int q0 = blockIdx.y * 64;
    const int tid = threadIdx.x;
    const int tx = tid & 15;
    const int ty = tid >> 4;

    const float* Qg = g_Q + (size_t)bh * SEQ * HD;
    const float* Kg = g_K + (size_t)bh * SEQ * HD;
    const float* Vg = g_V + (size_t)bh * SEQ * HD;

    // Load Q tile transposed, fold in softmax scale 1/sqrt(64) = 0.125
    #pragma unroll
    for (int i = 0; i < 16; i++) {
        int idx = tid + i * 256;          // 0..4095
        int r = idx >> 6, d = idx & 63;
        Qs[d * 68 + r] = Qg[(size_t)(q0 + r) * HD + d] * 0.125f;
    }
    if (tid < 64) { m_s[tid] = -1e30f; l_s[tid] = 0.0f; }

    float acc[4][4] = {};

    const int ktiles = (q0 >> 6) + 1;     // causal: only tiles with k0 <= q0
    for (int kt = 0; kt < ktiles; kt++) {
        const int k0 = kt * 64;
        __syncthreads();                  // prior PV done / Q load visible
        #pragma unroll
        for (int i = 0; i < 16; i++) {
            int idx = tid + i * 256;
            int c = idx >> 6, d = idx & 63;
            Ks[d * 68 + c] = Kg[(size_t)(k0 + c) * HD + d];
            Vs[c * 68 + d] = Vg[(size_t)(k0 + c) * HD + d];
        }
        __syncthreads();

        // S = Q K^T  (4x4 per thread)
        float s[4][4] = {};
        #pragma unroll
        for (int d = 0; d < 64; d++) {
            float4 av = *(const float4*)&Qs[d * 68 + ty * 4];
            float4 bv = *(const float4*)&Ks[d * 68 + tx * 4];
            float a[4] = {av.x, av.y, av.z, av.w};
            float b[4] = {bv.x, bv.y, bv.z, bv.w};
            #pragma unroll
            for (int i = 0; i < 4; i++)
                #pragma unroll
                for (int j = 0; j < 4; j++)
                    s[i][j] += a[i] * b[j];
        }

        // causal mask (only the diagonal tile can mask)
        if (kt == ktiles - 1) {
            #pragma unroll
            for (int i = 0; i < 4; i++)
                #pragma unroll
                for (int j = 0; j < 4; j++)
                    if (k0 + tx * 4 + j > q0 + ty * 4 + i) s[i][j] = -1e30f;
        }

        // store S transposed: Ps[col][row]
        #pragma unroll
        for (int i = 0; i < 4; i++)
            #pragma unroll
            for (int j = 0; j < 4; j++)
                Ps[(tx * 4 + j) * 68 + (ty * 4 + i)] = s[i][j];
        __syncthreads();

        // online softmax row pass: one thread per row
        if (tid < 64) {
            const int r = tid;
            float mo = m_s[r];
            float tm = -1e30f;
            #pragma unroll 8
            for (int j = 0; j < 64; j++) tm = fmaxf(tm, Ps[j * 68 + r]);
            float mn = fmaxf(mo, tm);
            float alpha = __expf(mo - mn);
            float lsum = 0.0f;
            #pragma unroll 8
            for (int j = 0; j < 64; j++) {
                float p = __expf(Ps[j * 68 + r] - mn);
                Ps[j * 68 + r] = p;
                lsum += p;
            }
            m_s[r] = mn;
            l_s[r] = l_s[r] * alpha + lsum;
            a_s[r] = alpha;
        }
        __syncthreads();

        // rescale accumulator, then O += P V
        float alr[4];
        #pragma unroll
        for (int i = 0; i < 4; i++) alr[i] = a_s[ty * 4 + i];
        #pragma unroll
        for (int i = 0; i < 4; i++)
            #pragma unroll
            for (int j = 0; j < 4; j++)
                acc[i][j] *= alr[i];

        #pragma unroll
        for (int jj = 0; jj < 64; jj++) {
            float4 av = *(const float4*)&Ps[jj * 68 + ty * 4];
            float4 bv = *(const float4*)&Vs[jj * 68 + tx * 4];
            float a[4] = {av.x, av.y, av.z, av.w};
            float b[4] = {bv.x, bv.y, bv.z, bv.w};
            #pragma unroll
            for (int i = 0; i < 4; i++)
                #pragma unroll
                for (int j = 0; j < 4; j++)
                    acc[i][j] += a[i] * b[j];
        }
    }

    // write O / l  to g_AO in (b, n, h*64+d) layout
    const int b = bh >> 3, h = bh & 7;
    #pragma unroll
    for (int i = 0; i < 4; i++) {
        int r = ty * 4 + i;
        float inv = 1.0f / l_s[r];
        float4 v = make_float4(acc[i][0] * inv, acc[i][1] * inv,
                               acc[i][2] * inv, acc[i][3] * inv);
        *(float4*)&g_AO[((size_t)(b * SEQ + q0 + r)) * EMB + h * HD + tx * 4] = v;
    }
}

// ---------------------------------------------------------------------------

extern "C" void kernel_launch(void* const* d_in, const int* in_sizes, int n_in,
                              void* d_out, int out_size)
{
    const float* x  = (const float*)d_in[0];
    const float* WQ = (const float*)d_in[1];
    const float* WK = (const float*)d_in[2];
    const float* WV = (const float*)d_in[3];
    const float* WO = (const float*)d_in[4];
    // d_in[5] = mask (int32 tril) — causal, applied analytically in-kernel.
    float* out = (float*)d_out;

    const int SMEM_ATTN = (4 * 64 * 68 + 3 * 64) * (int)sizeof(float); // 70400 B
    cudaFuncSetAttribute(attn_kernel,
                         cudaFuncAttributeMaxDynamicSharedMemorySize, SMEM_ATTN);

    dim3 gg(EMB / 64, MROWS / 64);   // (8, 128)

    // Q, K, V projections
    gemm_nt<<<gg, 256>>>(x, WQ, nullptr, 0);
    gemm_nt<<<gg, 256>>>(x, WK, nullptr, 1);
    gemm_nt<<<gg, 256>>>(x, WV, nullptr, 2);

    // flash attention: 32 (b,h) x 32 q-tiles
    attn_kernel<<<dim3(BATCH * NH, SEQ / 64), 256, SMEM_ATTN>>>();

    // output projection (A=nullptr -> reads g_AO)
    gemm_nt<<<gg, 256>>>(nullptr, WO, out, 3);
}

// round 3
// speedup vs baseline: 2.5847x; 2.5847x over previous
#include <cuda_runtime.h>
#include <math.h>

#define BATCH 4
#define SEQ   2048
#define EMB   512
#define NH    8
#define HD    64
#define MROWS (BATCH*SEQ)   // 8192

// Scratch (device globals: allocation-free per harness rules)
__device__ float g_Q[BATCH*NH*SEQ*HD];   // (b,h,n,d)
__device__ float g_K[BATCH*NH*SEQ*HD];
__device__ float g_V[BATCH*NH*SEQ*HD];
__device__ float g_AO[BATCH*SEQ*EMB];    // (b,n,e) attention output

// ---------------------------------------------------------------------------
// tf32 helpers
// ---------------------------------------------------------------------------
__device__ __forceinline__ unsigned f2tf(float f) {
    unsigned u; asm("cvt.rna.tf32.f32 %0, %1;" : "=r"(u) : "f"(f)); return u;
}
__device__ __forceinline__ float tfbits(float f) {
    return __uint_as_float(f2tf(f));
}
// D = A(16x8 row) * B(8x8 col) + D, tf32 in, fp32 out
__device__ __forceinline__ void mma8(float* c, const unsigned* a, const unsigned* b) {
    asm volatile(
        "mma.sync.aligned.m16n8k8.row.col.f32.tf32.tf32.f32 "
        "{%0,%1,%2,%3}, {%4,%5,%6,%7}, {%8,%9}, {%0,%1,%2,%3};"
        : "+f"(c[0]), "+f"(c[1]), "+f"(c[2]), "+f"(c[3])
        : "r"(a[0]), "r"(a[1]), "r"(a[2]), "r"(a[3]), "r"(b[0]), "r"(b[1]));
}

// ---------------------------------------------------------------------------
// GEMM: C[m,e] = sum_k A[m,k] * W[e,k]   (A: MROWS x 512, W: 512 x 512, both row-major)
// CTA tile 128x128, BK=16. 8 warps, warp tile 64x32 (4x4 tiles of m16n8).
// mode 0/1/2 -> scatter into g_Q/g_K/g_V (b,h,n,d); mode 3 -> row-major dout.
// ---------------------------------------------------------------------------
#define SA 20   // smem row stride (floats) for [row][k] tiles

__global__ __launch_bounds__(256) void gemm_tc(const float* __restrict__ A,
                                               const float* __restrict__ W,
                                               float* __restrict__ dout,
                                               int mode)
{
    __shared__ float As[128 * SA];
    __shared__ float Ws[128 * SA];

    const float* Ap = A ? A : g_AO;

    const int m0 = blockIdx.y * 128;
    const int e0 = blockIdx.x * 128;
    const int tid  = threadIdx.x;
    const int lane = tid & 31;
    const int wid  = tid >> 5;
    const int wy = wid >> 2;          // 0..1  (m offset wy*64)
    const int wx = wid & 3;           // 0..3  (n offset wx*32)
    const int r4 = lane >> 2;         // 0..7
    const int c4 = lane & 3;          // 0..3

    const int rowL = tid >> 1;        // 0..127 loader row
    const int kOff = (tid & 1) * 8;   // 0 or 8

    float acc[4][4][4] = {};          // [mi][ni][frag]

    for (int k0 = 0; k0 < EMB; k0 += 16) {
        float4 a0 = *(const float4*)&Ap[(size_t)(m0 + rowL) * EMB + k0 + kOff];
        float4 a1 = *(const float4*)&Ap[(size_t)(m0 + rowL) * EMB + k0 + kOff + 4];
        float4 w0 = *(const float4*)&W [(size_t)(e0 + rowL) * EMB + k0 + kOff];
        float4 w1 = *(const float4*)&W [(size_t)(e0 + rowL) * EMB + k0 + kOff + 4];
        __syncthreads();
        float* ad = &As[rowL * SA + kOff];
        ad[0] = tfbits(a0.x); ad[1] = tfbits(a0.y); ad[2] = tfbits(a0.z); ad[3] = tfbits(a0.w);
        ad[4] = tfbits(a1.x); ad[5] = tfbits(a1.y); ad[6] = tfbits(a1.z); ad[7] = tfbits(a1.w);
        float* wd = &Ws[rowL * SA + kOff];
        wd[0] = tfbits(w0.x); wd[1] = tfbits(w0.y); wd[2] = tfbits(w0.z); wd[3] = tfbits(w0.w);
        wd[4] = tfbits(w1.x); wd[5] = tfbits(w1.y); wd[6] = tfbits(w1.z); wd[7] = tfbits(w1.w);
        __syncthreads();

        #pragma unroll
        for (int ks = 0; ks < 16; ks += 8) {
            unsigned a[4][4], b[4][2];
            #pragma unroll
            for (int mi = 0; mi < 4; mi++) {
                int mr = wy * 64 + mi * 16;
                a[mi][0] = __float_as_uint(As[(mr + r4    ) * SA + ks + c4    ]);
                a[mi][1] = __float_as_uint(As[(mr + r4 + 8) * SA + ks + c4    ]);
                a[mi][2] = __float_as_uint(As[(mr + r4    ) * SA + ks + c4 + 4]);
                a[mi][3] = __float_as_uint(As[(mr + r4 + 8) * SA + ks + c4 + 4]);
            }
            #pragma unroll
            for (int ni = 0; ni < 4; ni++) {
                int n = wx * 32 + ni * 8 + r4;
                b[ni][0] = __float_as_uint(Ws[n * SA + ks + c4    ]);
                b[ni][1] = __float_as_uint(Ws[n * SA + ks + c4 + 4]);
            }
            #pragma unroll
            for (int mi = 0; mi < 4; mi++)
                #pragma unroll
                for (int ni = 0; ni < 4; ni++)
                    mma8(acc[mi][ni], a[mi], b[ni]);
        }
    }

    // epilogue
    #pragma unroll
    for (int mi = 0; mi < 4; mi++) {
        #pragma unroll
        for (int ni = 0; ni < 4; ni++) {
            int mlo = m0 + wy * 64 + mi * 16 + r4;
            int e   = e0 + wx * 32 + ni * 8 + c4 * 2;
            float2 vlo = make_float2(acc[mi][ni][0], acc[mi][ni][1]);
            float2 vhi = make_float2(acc[mi][ni][2], acc[mi][ni][3]);
            if (mode == 3) {
                *(float2*)&dout[(size_t)mlo * EMB + e]       = vlo;
                *(float2*)&dout[(size_t)(mlo + 8) * EMB + e] = vhi;
            } else {
                float* dst = (mode == 0) ? g_Q : (mode == 1) ? g_K : g_V;
                int h = e >> 6, d = e & 63;
                int b0 = mlo >> 11, n0 = mlo & (SEQ - 1);
                *(float2*)&dst[((size_t)(b0 * NH + h) * SEQ + n0) * HD + d] = vlo;
                int m2 = mlo + 8;
                int b1 = m2 >> 11, n1 = m2 & (SEQ - 1);
                *(float2*)&dst[((size_t)(b1 * NH + h) * SEQ + n1) * HD + d] = vhi;
            }
        }
    }
}

// ---------------------------------------------------------------------------
// Causal flash attention with tf32 mma. One CTA = (b,h) x 128 query rows.
// 8 warps, each owns 16 q-rows and the full 64-wide k tile.
// Smem (floats, stride STQ=68):
//   Qs[128][64]  A-operand, prescaled by 0.125, tf32-rounded
//   Ks[64][64]   B-operand for QK^T (c,d natural)
//   Vt[64][64]   B-operand for PV   (transposed: [d][c])
//   Ps[8][16][64] per-warp P staging
// ---------------------------------------------------------------------------
#define STQ 68

__global__ __launch_bounds__(256) void attn_tc()
{
    extern __shared__ float smx[];
    float* Qs = smx;                 // 128*STQ
    float* Ks = Qs + 128 * STQ;      // 64*STQ
    float* Vt = Ks + 64 * STQ;       // 64*STQ
    float* Ps = Vt + 64 * STQ;       // 128*STQ

    const int bh = blockIdx.x;       // 0..31
    const int q0 = blockIdx.y * 128;
    const int tid  = threadIdx.x;
    const int lane = tid & 31;
    const int wid  = tid >> 5;
    const int r4 = lane >> 2;
    const int c4 = lane & 3;

    const float* Qg = g_Q + (size_t)bh * SEQ * HD;
    const float* Kg = g_K + (size_t)bh * SEQ * HD;
    const float* Vg = g_V + (size_t)bh * SEQ * HD;

    // load Q tile (prescale by 1/sqrt(64) = 0.125)
    #pragma unroll
    for (int i = 0; i < 8; i++) {
        int idx = tid + i * 256;             // over 2048 float4s
        int r = idx >> 4, d4 = (idx & 15) * 4;
        float4 v = *(const float4*)&Qg[(size_t)(q0 + r) * HD + d4];
        float* qd = &Qs[r * STQ + d4];
        qd[0] = tfbits(v.x * 0.125f); qd[1] = tfbits(v.y * 0.125f);
        qd[2] = tfbits(v.z * 0.125f); qd[3] = tfbits(v.w * 0.125f);
    }

    float m0r = -1e30f, m1r = -1e30f;        // row stats: rows r4, r4+8 of this warp
    float l0r = 0.0f,  l1r = 0.0f;
    float o[8][4] = {};                      // O acc: 8 d-tiles x 4 frags

    float* Pw = Ps + wid * 16 * STQ;
    const int ktiles = (q0 >> 6) + 2;        // causal
    const int maskStart = ktiles - 2;

    for (int kt = 0; kt < ktiles; kt++) {
        const int k0 = kt * 64;
        __syncthreads();
        // load K (natural) and V (transposed)
        #pragma unroll
        for (int i = 0; i < 4; i++) {
            int idx = tid + i * 256;         // over 1024 float4s
            int c = idx >> 4, d4 = (idx & 15) * 4;
            float4 kv = *(const float4*)&Kg[(size_t)(k0 + c) * HD + d4];
            float* kd = &Ks[c * STQ + d4];
            kd[0] = tfbits(kv.x); kd[1] = tfbits(kv.y);
            kd[2] = tfbits(kv.z); kd[3] = tfbits(kv.w);
            float4 vv = *(const float4*)&Vg[(size_t)(k0 + c) * HD + d4];
            Vt[(d4 + 0) * STQ + c] = tfbits(vv.x);
            Vt[(d4 + 1) * STQ + c] = tfbits(vv.y);
            Vt[(d4 + 2) * STQ + c] = tfbits(vv.z);
            Vt[(d4 + 3) * STQ + c] = tfbits(vv.w);
        }
        __syncthreads();

        // S = Q K^T : warp computes 16x64
        float s[8][4] = {};
        #pragma unroll
        for (int ks = 0; ks < 64; ks += 8) {
            unsigned a[4];
            int qr = wid * 16;
            a[0] = __float_as_uint(Qs[(qr + r4    ) * STQ + ks + c4    ]);
            a[1] = __float_as_uint(Qs[(qr + r4 + 8) * STQ + ks + c4    ]);
            a[2] = __float_as_uint(Qs[(qr + r4    ) * STQ + ks + c4 + 4]);
            a[3] = __float_as_uint(Qs[(qr + r4 + 8) * STQ + ks + c4 + 4]);
            #pragma unroll
            for (int ni = 0; ni < 8; ni++) {
                unsigned b[2];
                int n = ni * 8 + r4;
                b[0] = __float_as_uint(Ks[n * STQ + ks + c4    ]);
                b[1] = __float_as_uint(Ks[n * STQ + ks + c4 + 4]);
                mma8(s[ni], a, b);
            }
        }

        // causal mask (only last two tiles can clip)
        if (kt >= maskStart) {
            int grow = q0 + wid * 16 + r4;
            #pragma unroll
            for (int ni = 0; ni < 8; ni++) {
                int gcol = k0 + ni * 8 + c4 * 2;
                if (gcol     > grow    ) s[ni][0] = -1e30f;
                if (gcol + 1 > grow    ) s[ni][1] = -1e30f;
                if (gcol     > grow + 8) s[ni][2] = -1e30f;
                if (gcol + 1 > grow + 8) s[ni][3] = -1e30f;
            }
        }

        // online softmax (2 rows per thread, quad reduce over lanes)
        float mx0 = -1e30f, mx1 = -1e30f;
        #pragma unroll
        for (int ni = 0; ni < 8; ni++) {
            mx0 = fmaxf(mx0, fmaxf(s[ni][0], s[ni][1]));
            mx1 = fmaxf(mx1, fmaxf(s[ni][2], s[ni][3]));
        }
        mx0 = fmaxf(mx0, __shfl_xor_sync(0xffffffffu, mx0, 1));
        mx0 = fmaxf(mx0, __shfl_xor_sync(0xffffffffu, mx0, 2));
        mx1 = fmaxf(mx1, __shfl_xor_sync(0xffffffffu, mx1, 1));
        mx1 = fmaxf(mx1, __shfl_xor_sync(0xffffffffu, mx1, 2));
        float mn0 = fmaxf(m0r, mx0), mn1 = fmaxf(m1r, mx1);
        float al0 = __expf(m0r - mn0), al1 = __expf(m1r - mn1);
        float ls0 = 0.0f, ls1 = 0.0f;
        #pragma unroll
        for (int ni = 0; ni < 8; ni++) {
            s[ni][0] = __expf(s[ni][0] - mn0);
            s[ni][1] = __expf(s[ni][1] - mn0);
            s[ni][2] = __expf(s[ni][2] - mn1);
            s[ni][3] = __expf(s[ni][3] - mn1);
            ls0 += s[ni][0] + s[ni][1];
            ls1 += s[ni][2] + s[ni][3];
        }
        ls0 += __shfl_xor_sync(0xffffffffu, ls0, 1);
        ls0 += __shfl_xor_sync(0xffffffffu, ls0, 2);
        ls1 += __shfl_xor_sync(0xffffffffu, ls1, 1);
        ls1 += __shfl_xor_sync(0xffffffffu, ls1, 2);
        l0r = l0r * al0 + ls0;  m0r = mn0;
        l1r = l1r * al1 + ls1;  m1r = mn1;

        #pragma unroll
        for (int ni = 0; ni < 8; ni++) {
            o[ni][0] *= al0; o[ni][1] *= al0;
            o[ni][2] *= al1; o[ni][3] *= al1;
        }

        // stage P (tf32) into this warp's private smem region
        #pragma unroll
        for (int ni = 0; ni < 8; ni++) {
            int col = ni * 8 + c4 * 2;
            Pw[(r4    ) * STQ + col    ] = tfbits(s[ni][0]);
            Pw[(r4    ) * STQ + col + 1] = tfbits(s[ni][1]);
            Pw[(r4 + 8) * STQ + col    ] = tfbits(s[ni][2]);
            Pw[(r4 + 8) * STQ + col + 1] = tfbits(s[ni][3]);
        }
        __syncwarp();

        // O += P @ V
        #pragma unroll
        for (int ks = 0; ks < 64; ks += 8) {
            unsigned a[4];
            a[0] = __float_as_uint(Pw[(r4    ) * STQ + ks + c4    ]);
            a[1] = __float_as_uint(Pw[(r4 + 8) * STQ + ks + c4    ]);
            a[2] = __float_as_uint(Pw[(r4    ) * STQ + ks + c4 + 4]);
            a[3] = __float_as_uint(Pw[(r4 + 8) * STQ + ks + c4 + 4]);
            #pragma unroll
            for (int ni = 0; ni < 8; ni++) {
                unsigned b[2];
                int n = ni * 8 + r4;       // d index
                b[0] = __float_as_uint(Vt[n * STQ + ks + c4    ]);
                b[1] = __float_as_uint(Vt[n * STQ + ks + c4 + 4]);
                mma8(o[ni], a, b);
            }
        }
        __syncwarp();
    }

    // epilogue: divide by l, write to g_AO (b, n, h*64+d)
    float inv0 = 1.0f / l0r, inv1 = 1.0f / l1r;
    const int b = bh >> 3, h = bh & 7;
    const int row0 = q0 + wid * 16 + r4;
    #pragma unroll
    for (int ni = 0; ni < 8; ni++) {
        int e = h * 64 + ni * 8 + c4 * 2;
        float2 vlo = make_float2(o[ni][0] * inv0, o[ni][1] * inv0);
        float2 vhi = make_float2(o[ni][2] * inv1, o[ni][3] * inv1);
        *(float2*)&g_AO[(size_t)(b * SEQ + row0    ) * EMB + e] = vlo;
        *(float2*)&g_AO[(size_t)(b * SEQ + row0 + 8) * EMB + e] = vhi;
    }
}

// ---------------------------------------------------------------------------

extern "C" void kernel_launch(void* const* d_in, const int* in_sizes, int n_in,
                              void* d_out, int out_size)
{
    const float* x  = (const float*)d_in[0];
    const float* WQ = (const float*)d_in[1];
    const float* WK = (const float*)d_in[2];
    const float* WV = (const float*)d_in[3];
    const float* WO = (const float*)d_in[4];
    // d_in[5] = mask (tril) — causal, applied analytically in-kernel.
    float* out = (float*)d_out;

    const int SMEM_ATTN = 384 * STQ * (int)sizeof(float);   // 104448 B
    static bool attr_set = false;
    if (!attr_set) {
        cudaFuncSetAttribute(attn_tc,
                             cudaFuncAttributeMaxDynamicSharedMemorySize, SMEM_ATTN);
        attr_set = true;
    }

    dim3 gg(EMB / 128, MROWS / 128);   // (4, 64)

    gemm_tc<<<gg, 256>>>(x, WQ, nullptr, 0);
    gemm_tc<<<gg, 256>>>(x, WK, nullptr, 1);
    gemm_tc<<<gg, 256>>>(x, WV, nullptr, 2);

    attn_tc<<<dim3(BATCH * NH, SEQ / 128), 256, SMEM_ATTN>>>();

    gemm_tc<<<gg, 256>>>(nullptr, WO, out, 3);
}